// round 1
// baseline (speedup 1.0000x reference)
#include <cuda_runtime.h>

#define NN   50000
#define EE   1600000
#define BB   64
#define DD   128
#define LL   3
#define OUTD 64

// ---------------- scratch (static device allocations; no cudaMalloc) ----------------
__device__ int   g_deg[NN];
__device__ int   g_offs[NN + 1];
__device__ int   g_cursor[NN];
__device__ int   g_csr[EE];
__device__ int   g_counts[BB];
__device__ float g_G[LL * DD];
__device__ float g_z[NN * DD];
__device__ float g_h[LL][NN * DD];

// ---------------- setup kernels ----------------
__global__ void zero_kernel() {
    int i = blockIdx.x * blockDim.x + threadIdx.x;
    if (i < NN) g_deg[i] = 0;
    if (i < BB) g_counts[i] = 0;
    if (i < LL * DD) g_G[i] = 0.f;
}

__global__ void hist_kernel(const int* __restrict__ dst) {
    int i = blockIdx.x * blockDim.x + threadIdx.x;
    if (i < EE) atomicAdd(&g_deg[dst[i]], 1);
}

__global__ void batch_hist_kernel(const int* __restrict__ batch) {
    __shared__ int loc[BB];
    if (threadIdx.x < BB) loc[threadIdx.x] = 0;
    __syncthreads();
    for (int i = blockIdx.x * blockDim.x + threadIdx.x; i < NN; i += gridDim.x * blockDim.x)
        atomicAdd(&loc[batch[i]], 1);
    __syncthreads();
    if (threadIdx.x < BB) atomicAdd(&g_counts[threadIdx.x], loc[threadIdx.x]);
}

// single-block exclusive scan of degrees -> CSR offsets (+ cursor copy)
__global__ void scan_kernel() {
    const int T = 1024;
    int tid = threadIdx.x;
    const int chunk = (NN + T - 1) / T;  // 49
    int start = tid * chunk;
    int end   = min(start + chunk, NN);
    int s = 0;
    for (int i = start; i < end; i++) s += g_deg[i];
    __shared__ int ps[T];
    ps[tid] = s;
    __syncthreads();
    for (int d = 1; d < T; d <<= 1) {
        int v = (tid >= d) ? ps[tid - d] : 0;
        __syncthreads();
        ps[tid] += v;
        __syncthreads();
    }
    int run = ps[tid] - s;  // exclusive prefix
    for (int i = start; i < end; i++) {
        g_offs[i]   = run;
        g_cursor[i] = run;
        run += g_deg[i];
    }
    if (tid == T - 1) g_offs[NN] = run;
}

__global__ void scatter_kernel(const int* __restrict__ src, const int* __restrict__ dst) {
    int i = blockIdx.x * blockDim.x + threadIdx.x;
    if (i < EE) {
        int p = atomicAdd(&g_cursor[dst[i]], 1);
        g_csr[p] = src[i];
    }
}

// ---------------- aggregation: warp per node, gather-sum over CSR ----------------
__global__ void agg_kernel(const float* __restrict__ x, const float* __restrict__ eps, int l) {
    int gw = (blockIdx.x * blockDim.x + threadIdx.x) >> 5;
    if (gw >= NN) return;
    int lane = threadIdx.x & 31;
    const float* hin = (l == 0) ? x : g_h[l - 1];
    float ep1 = 1.0f + eps[l];
    const float4* hp = (const float4*)hin;
    float4 self = hp[(size_t)gw * (DD / 4) + lane];
    float4 acc;
    acc.x = self.x * ep1; acc.y = self.y * ep1; acc.z = self.z * ep1; acc.w = self.w * ep1;
    int s = g_offs[gw], e = g_offs[gw + 1];
    for (int j = s; j < e; j++) {
        int src = g_csr[j];  // uniform across warp
        float4 v = hp[(size_t)src * (DD / 4) + lane];
        acc.x += v.x; acc.y += v.y; acc.z += v.z; acc.w += v.w;
    }
    ((float4*)g_z)[(size_t)gw * (DD / 4) + lane] = acc;
}

// ---------------- fused per-layer MLP: h = relu(z@W1+b1)@W2+b2 ----------------
// block = 256 threads, 64-row tile, full 128x128 weight in smem.
__global__ __launch_bounds__(256, 2) void mlp_kernel(
    int l,
    const float* __restrict__ W1g, const float* __restrict__ b1g,
    const float* __restrict__ W2g, const float* __restrict__ b2g) {
    extern __shared__ float smem[];
    float* zs = smem;             // [64][128]
    float* ws = smem + 64 * DD;   // [128][128]
    const float* W1 = W1g + (size_t)l * DD * DD;
    const float* W2 = W2g + (size_t)l * DD * DD;
    const float* b1 = b1g + l * DD;
    const float* b2 = b2g + l * DD;
    float* hout = g_h[l];

    int tid = threadIdx.x;
    int m0  = blockIdx.x * 64;
    int cg  = tid & 31;   // float4 column group
    int rg  = tid >> 5;   // 0..7

    // load z tile
#pragma unroll
    for (int i = 0; i < 8; i++) {
        int r = rg + i * 8;
        int row = m0 + r;
        float4 v = make_float4(0.f, 0.f, 0.f, 0.f);
        if (row < NN) v = *(const float4*)(g_z + (size_t)row * DD + cg * 4);
        *(float4*)(zs + r * DD + cg * 4) = v;
    }
    // load W1
#pragma unroll
    for (int i = 0; i < 16; i++) {
        int r = rg + i * 8;
        *(float4*)(ws + r * DD + cg * 4) = *(const float4*)(W1 + r * DD + cg * 4);
    }
    __syncthreads();

    int mB = rg * 8;
    int nB = cg * 4;
    float acc[8][4];
#pragma unroll
    for (int mi = 0; mi < 8; mi++)
#pragma unroll
        for (int ni = 0; ni < 4; ni++) acc[mi][ni] = 0.f;

#pragma unroll 8
    for (int k = 0; k < DD; k++) {
        float4 b = *(float4*)(ws + k * DD + nB);
#pragma unroll
        for (int mi = 0; mi < 8; mi++) {
            float a = zs[(mB + mi) * DD + k];
            acc[mi][0] += a * b.x;
            acc[mi][1] += a * b.y;
            acc[mi][2] += a * b.z;
            acc[mi][3] += a * b.w;
        }
    }
    __syncthreads();  // everyone done reading zs/ws

    // t = relu(acc + b1) -> back into zs
    {
        float4 bb = *(const float4*)(b1 + nB);
#pragma unroll
        for (int mi = 0; mi < 8; mi++) {
            float4 t;
            t.x = fmaxf(acc[mi][0] + bb.x, 0.f);
            t.y = fmaxf(acc[mi][1] + bb.y, 0.f);
            t.z = fmaxf(acc[mi][2] + bb.z, 0.f);
            t.w = fmaxf(acc[mi][3] + bb.w, 0.f);
            *(float4*)(zs + (mB + mi) * DD + nB) = t;
        }
    }
    // load W2 (ws free after sync above)
#pragma unroll
    for (int i = 0; i < 16; i++) {
        int r = rg + i * 8;
        *(float4*)(ws + r * DD + cg * 4) = *(const float4*)(W2 + r * DD + cg * 4);
    }
    __syncthreads();

#pragma unroll
    for (int mi = 0; mi < 8; mi++)
#pragma unroll
        for (int ni = 0; ni < 4; ni++) acc[mi][ni] = 0.f;

#pragma unroll 8
    for (int k = 0; k < DD; k++) {
        float4 b = *(float4*)(ws + k * DD + nB);
#pragma unroll
        for (int mi = 0; mi < 8; mi++) {
            float a = zs[(mB + mi) * DD + k];
            acc[mi][0] += a * b.x;
            acc[mi][1] += a * b.y;
            acc[mi][2] += a * b.z;
            acc[mi][3] += a * b.w;
        }
    }

    {
        float4 bb = *(const float4*)(b2 + nB);
#pragma unroll
        for (int mi = 0; mi < 8; mi++) {
            int row = m0 + mB + mi;
            if (row < NN) {
                float4 o;
                o.x = acc[mi][0] + bb.x;
                o.y = acc[mi][1] + bb.y;
                o.z = acc[mi][2] + bb.z;
                o.w = acc[mi][3] + bb.w;
                *(float4*)(hout + (size_t)row * DD + nB) = o;
            }
        }
    }
}

// ---------------- pooling: G[l*128+c] = sum_i h_l[i][c] / count[batch[i]] ----------------
__global__ void pool_kernel(const int* __restrict__ batch) {
    __shared__ float inv[BB];
    int tid = threadIdx.x;  // 384 threads
    if (tid < BB) inv[tid] = 1.f / (float)max(g_counts[tid], 1);
    __syncthreads();
    int layer = tid >> 7;
    int col   = tid & 127;
    const float* h = g_h[layer];
    float acc = 0.f;
    for (int row = blockIdx.x; row < NN; row += gridDim.x)
        acc += h[(size_t)row * DD + col] * inv[batch[row]];
    atomicAdd(&g_G[tid], acc);
}

// ---------------- final tiny MLP: out = relu(relu(G@l1w+l1b)@l2w+l2b) ----------------
__global__ void final_kernel(const float* __restrict__ l1w, const float* __restrict__ l1b,
                             const float* __restrict__ l2w, const float* __restrict__ l2b,
                             float* __restrict__ out) {
    __shared__ float Gs[LL * DD];
    __shared__ float g1[DD];
    int tid = threadIdx.x;  // 128
    for (int i = tid; i < LL * DD; i += 128) Gs[i] = g_G[i];
    __syncthreads();
    float acc = l1b[tid];
    for (int k = 0; k < LL * DD; k++) acc += Gs[k] * l1w[k * DD + tid];
    g1[tid] = fmaxf(acc, 0.f);
    __syncthreads();
    if (tid < OUTD) {
        float a2 = l2b[tid];
        for (int k = 0; k < DD; k++) a2 += g1[k] * l2w[k * OUTD + tid];
        out[tid] = fmaxf(a2, 0.f);
    }
}

// ---------------- launch ----------------
extern "C" void kernel_launch(void* const* d_in, const int* in_sizes, int n_in,
                              void* d_out, int out_size) {
    const float* x    = (const float*)d_in[0];
    const int*   ei   = (const int*)d_in[1];
    const int*   batch= (const int*)d_in[2];
    const float* eps  = (const float*)d_in[3];
    const float* W1   = (const float*)d_in[4];
    const float* b1   = (const float*)d_in[5];
    const float* W2   = (const float*)d_in[6];
    const float* b2   = (const float*)d_in[7];
    const float* l1w  = (const float*)d_in[8];
    const float* l1b  = (const float*)d_in[9];
    const float* l2w  = (const float*)d_in[10];
    const float* l2b  = (const float*)d_in[11];
    float* out = (float*)d_out;

    cudaFuncSetAttribute(mlp_kernel, cudaFuncAttributeMaxDynamicSharedMemorySize, 98304);

    zero_kernel<<<(NN + 255) / 256, 256>>>();
    hist_kernel<<<(EE + 255) / 256, 256>>>(ei + EE);
    batch_hist_kernel<<<64, 256>>>(batch);
    scan_kernel<<<1, 1024>>>();
    scatter_kernel<<<(EE + 255) / 256, 256>>>(ei, ei + EE);

    for (int l = 0; l < LL; l++) {
        agg_kernel<<<(NN * 32 + 255) / 256, 256>>>(x, eps, l);
        mlp_kernel<<<(NN + 63) / 64, 256, 98304>>>(l, W1, b1, W2, b2);
    }

    pool_kernel<<<256, 384>>>(batch);
    final_kernel<<<1, 128>>>(l1w, l1b, l2w, l2b, out);
}

// round 2
// speedup vs baseline: 1.5914x; 1.5914x over previous
#include <cuda_runtime.h>
#include <cstdint>

#define NN   50000
#define EE   1600000
#define BB   64
#define DD   128
#define LL   3
#define OUTD 64

#define SCAN_B 196          // ceil(50000/256)

// ---------------- scratch (static device allocations) ----------------
__device__ int   g_deg[NN];
__device__ int   g_offs[NN + 1];
__device__ int   g_cursor[NN];
__device__ int   g_csr[EE];
__device__ int   g_counts[BB];
__device__ int   g_bsum[SCAN_B];
__device__ int   g_bbase[SCAN_B];
__device__ float g_G[LL * DD];
__device__ float g_z[NN * DD];
__device__ float g_h[LL][NN * DD];

// ---------------- setup kernels ----------------
__global__ void zero_kernel() {
    int i = blockIdx.x * blockDim.x + threadIdx.x;
    if (i < NN) g_deg[i] = 0;
    if (i < BB) g_counts[i] = 0;
    if (i < LL * DD) g_G[i] = 0.f;
}

__global__ void hist_kernel(const int* __restrict__ dst) {
    int i = blockIdx.x * blockDim.x + threadIdx.x;
    if (i < EE) atomicAdd(&g_deg[dst[i]], 1);
}

__global__ void batch_hist_kernel(const int* __restrict__ batch) {
    __shared__ int loc[BB];
    if (threadIdx.x < BB) loc[threadIdx.x] = 0;
    __syncthreads();
    for (int i = blockIdx.x * blockDim.x + threadIdx.x; i < NN; i += gridDim.x * blockDim.x)
        atomicAdd(&loc[batch[i]], 1);
    __syncthreads();
    if (threadIdx.x < BB) atomicAdd(&g_counts[threadIdx.x], loc[threadIdx.x]);
}

// ---- parallel scan: S1 block sums, S2 scan of sums, S3 per-block rescan ----
__global__ void scan1_kernel() {
    int i = blockIdx.x * 256 + threadIdx.x;
    int v = (i < NN) ? g_deg[i] : 0;
#pragma unroll
    for (int d = 16; d > 0; d >>= 1) v += __shfl_down_sync(0xffffffffu, v, d);
    __shared__ int ws[8];
    if ((threadIdx.x & 31) == 0) ws[threadIdx.x >> 5] = v;
    __syncthreads();
    if (threadIdx.x < 8) {
        int t = ws[threadIdx.x];
#pragma unroll
        for (int d = 4; d > 0; d >>= 1) t += __shfl_down_sync(0xffu, t, d);
        if (threadIdx.x == 0) g_bsum[blockIdx.x] = t;
    }
}

__global__ void scan2_kernel() {
    __shared__ int sh[256];
    int tid = threadIdx.x;
    int v = (tid < SCAN_B) ? g_bsum[tid] : 0;
    sh[tid] = v;
    __syncthreads();
    for (int d = 1; d < 256; d <<= 1) {
        int t = (tid >= d) ? sh[tid - d] : 0;
        __syncthreads();
        sh[tid] += t;
        __syncthreads();
    }
    if (tid < SCAN_B) g_bbase[tid] = sh[tid] - v;
    if (tid == 0) g_offs[NN] = EE;
}

__global__ void scan3_kernel() {
    __shared__ int sh[256];
    int tid = threadIdx.x;
    int i = blockIdx.x * 256 + tid;
    int v = (i < NN) ? g_deg[i] : 0;
    sh[tid] = v;
    __syncthreads();
    for (int d = 1; d < 256; d <<= 1) {
        int t = (tid >= d) ? sh[tid - d] : 0;
        __syncthreads();
        sh[tid] += t;
        __syncthreads();
    }
    if (i < NN) {
        int o = g_bbase[blockIdx.x] + sh[tid] - v;
        g_offs[i] = o;
        g_cursor[i] = o;
    }
}

__global__ void scatter_kernel(const int* __restrict__ src, const int* __restrict__ dst) {
    int i = blockIdx.x * blockDim.x + threadIdx.x;
    if (i < EE) {
        int p = atomicAdd(&g_cursor[dst[i]], 1);
        g_csr[p] = src[i];
    }
}

// ---------------- aggregation: warp per node, gather over CSR, unrolled x4 ----------------
__global__ void agg_kernel(const float* __restrict__ x, const float* __restrict__ eps, int l) {
    int gw = (blockIdx.x * blockDim.x + threadIdx.x) >> 5;
    if (gw >= NN) return;
    int lane = threadIdx.x & 31;
    const float* hin = (l == 0) ? x : g_h[l - 1];
    float ep1 = 1.0f + eps[l];
    const float4* hp = (const float4*)hin;
    float4 self = hp[(size_t)gw * (DD / 4) + lane];
    float4 acc;
    acc.x = self.x * ep1; acc.y = self.y * ep1; acc.z = self.z * ep1; acc.w = self.w * ep1;
    int s = g_offs[gw], e = g_offs[gw + 1];
    int j = s;
    for (; j + 4 <= e; j += 4) {
        int s0 = g_csr[j], s1 = g_csr[j + 1], s2 = g_csr[j + 2], s3 = g_csr[j + 3];
        float4 v0 = hp[(size_t)s0 * 32 + lane];
        float4 v1 = hp[(size_t)s1 * 32 + lane];
        float4 v2 = hp[(size_t)s2 * 32 + lane];
        float4 v3 = hp[(size_t)s3 * 32 + lane];
        float4 p0, p1;
        p0.x = v0.x + v1.x; p0.y = v0.y + v1.y; p0.z = v0.z + v1.z; p0.w = v0.w + v1.w;
        p1.x = v2.x + v3.x; p1.y = v2.y + v3.y; p1.z = v2.z + v3.z; p1.w = v2.w + v3.w;
        acc.x += p0.x + p1.x; acc.y += p0.y + p1.y; acc.z += p0.z + p1.z; acc.w += p0.w + p1.w;
    }
    for (; j < e; j++) {
        int src = g_csr[j];
        float4 v = hp[(size_t)src * 32 + lane];
        acc.x += v.x; acc.y += v.y; acc.z += v.z; acc.w += v.w;
    }
    ((float4*)g_z)[(size_t)gw * (DD / 4) + lane] = acc;
}

// ---------------- TF32 tensor-core fused MLP ----------------
#define ZLD 132   // Zs row stride (floats): 132 % 32 == 4 -> A-frag conflict-free
#define WLD 136   // Ws row stride (floats): 136 % 32 == 8 -> B-frag conflict-free
#define MLP_SMEM ((128 * ZLD + 128 * WLD) * 4)

__device__ __forceinline__ uint32_t tf32r(float x) {
    uint32_t r;
    asm("cvt.rna.tf32.f32 %0, %1;" : "=r"(r) : "f"(x));
    return r;
}

__device__ __forceinline__ void mma_tf32(float c[4], const uint32_t a[4], const uint32_t b[2]) {
    asm volatile(
        "mma.sync.aligned.m16n8k8.row.col.f32.tf32.tf32.f32 "
        "{%0,%1,%2,%3}, {%4,%5,%6,%7}, {%8,%9}, {%0,%1,%2,%3};\n"
        : "+f"(c[0]), "+f"(c[1]), "+f"(c[2]), "+f"(c[3])
        : "r"(a[0]), "r"(a[1]), "r"(a[2]), "r"(a[3]), "r"(b[0]), "r"(b[1]));
}

// one 128x128x128 GEMM on smem tiles; acc += Zs @ Ws
__device__ __forceinline__ void gemm_tile(const float* __restrict__ Zs, const float* __restrict__ Ws,
                                          float acc[2][8][4], int wm, int wn, int lane) {
    int g = lane >> 2, t = lane & 3;
#pragma unroll
    for (int k0 = 0; k0 < 128; k0 += 8) {
        uint32_t a[2][4];
#pragma unroll
        for (int mt = 0; mt < 2; mt++) {
            int r0 = wm + mt * 16 + g;
            a[mt][0] = __float_as_uint(Zs[r0 * ZLD + k0 + t]);
            a[mt][1] = __float_as_uint(Zs[(r0 + 8) * ZLD + k0 + t]);
            a[mt][2] = __float_as_uint(Zs[r0 * ZLD + k0 + t + 4]);
            a[mt][3] = __float_as_uint(Zs[(r0 + 8) * ZLD + k0 + t + 4]);
        }
        uint32_t b[8][2];
#pragma unroll
        for (int nt = 0; nt < 8; nt++) {
            int c = wn + nt * 8 + g;
            b[nt][0] = __float_as_uint(Ws[(k0 + t) * WLD + c]);
            b[nt][1] = __float_as_uint(Ws[(k0 + 4 + t) * WLD + c]);
        }
#pragma unroll
        for (int mt = 0; mt < 2; mt++)
#pragma unroll
            for (int nt = 0; nt < 8; nt++)
                mma_tf32(acc[mt][nt], a[mt], b[nt]);
    }
}

__global__ __launch_bounds__(256, 1) void mlp_kernel(
    int l,
    const float* __restrict__ W1g, const float* __restrict__ b1g,
    const float* __restrict__ W2g, const float* __restrict__ b2g) {
    extern __shared__ float smem[];
    float* Zs = smem;               // [128][ZLD]
    float* Ws = smem + 128 * ZLD;   // [128][WLD]
    const float* W1 = W1g + (size_t)l * DD * DD;
    const float* W2 = W2g + (size_t)l * DD * DD;
    const float* b1 = b1g + l * DD;
    const float* b2 = b2g + l * DD;
    float* hout = g_h[l];

    int tid  = threadIdx.x;
    int lane = tid & 31;
    int w    = tid >> 5;
    int wm   = (w & 3) * 32;
    int wn   = (w >> 2) * 64;
    int m0   = blockIdx.x * 128;

    // cooperative load: Z tile (tf32-rounded) and W1
#pragma unroll
    for (int i = 0; i < 16; i++) {
        int idx = i * 256 + tid;        // 0..4095
        int row = idx >> 5;
        int c4  = (idx & 31) * 4;
        float4 v = make_float4(0.f, 0.f, 0.f, 0.f);
        if (m0 + row < NN) v = *(const float4*)(g_z + (size_t)(m0 + row) * DD + c4);
        float* dz = Zs + row * ZLD + c4;
        dz[0] = __uint_as_float(tf32r(v.x));
        dz[1] = __uint_as_float(tf32r(v.y));
        dz[2] = __uint_as_float(tf32r(v.z));
        dz[3] = __uint_as_float(tf32r(v.w));
        float4 wv = *(const float4*)(W1 + row * DD + c4);
        float* dw = Ws + row * WLD + c4;
        dw[0] = __uint_as_float(tf32r(wv.x));
        dw[1] = __uint_as_float(tf32r(wv.y));
        dw[2] = __uint_as_float(tf32r(wv.z));
        dw[3] = __uint_as_float(tf32r(wv.w));
    }
    __syncthreads();

    float acc[2][8][4];
#pragma unroll
    for (int mt = 0; mt < 2; mt++)
#pragma unroll
        for (int nt = 0; nt < 8; nt++)
#pragma unroll
            for (int i = 0; i < 4; i++) acc[mt][nt][i] = 0.f;

    gemm_tile(Zs, Ws, acc, wm, wn, lane);
    __syncthreads();   // all smem reads of GEMM1 done

    // epilogue1: relu(acc + b1) -> Zs (tf32-rounded); also reload Ws with W2
    {
        int g = lane >> 2, t = lane & 3;
#pragma unroll
        for (int nt = 0; nt < 8; nt++) {
            int col = wn + nt * 8 + 2 * t;
            float bx = __ldg(b1 + col), by = __ldg(b1 + col + 1);
#pragma unroll
            for (int mt = 0; mt < 2; mt++) {
                int r0 = wm + mt * 16 + g;
                Zs[r0 * ZLD + col]           = __uint_as_float(tf32r(fmaxf(acc[mt][nt][0] + bx, 0.f)));
                Zs[r0 * ZLD + col + 1]       = __uint_as_float(tf32r(fmaxf(acc[mt][nt][1] + by, 0.f)));
                Zs[(r0 + 8) * ZLD + col]     = __uint_as_float(tf32r(fmaxf(acc[mt][nt][2] + bx, 0.f)));
                Zs[(r0 + 8) * ZLD + col + 1] = __uint_as_float(tf32r(fmaxf(acc[mt][nt][3] + by, 0.f)));
            }
        }
    }
#pragma unroll
    for (int i = 0; i < 16; i++) {
        int idx = i * 256 + tid;
        int row = idx >> 5;
        int c4  = (idx & 31) * 4;
        float4 wv = *(const float4*)(W2 + row * DD + c4);
        float* dw = Ws + row * WLD + c4;
        dw[0] = __uint_as_float(tf32r(wv.x));
        dw[1] = __uint_as_float(tf32r(wv.y));
        dw[2] = __uint_as_float(tf32r(wv.z));
        dw[3] = __uint_as_float(tf32r(wv.w));
    }
    __syncthreads();

#pragma unroll
    for (int mt = 0; mt < 2; mt++)
#pragma unroll
        for (int nt = 0; nt < 8; nt++)
#pragma unroll
            for (int i = 0; i < 4; i++) acc[mt][nt][i] = 0.f;

    gemm_tile(Zs, Ws, acc, wm, wn, lane);

    // epilogue2: acc + b2 -> global h (fp32)
    {
        int g = lane >> 2, t = lane & 3;
#pragma unroll
        for (int nt = 0; nt < 8; nt++) {
            int col = wn + nt * 8 + 2 * t;
            float bx = __ldg(b2 + col), by = __ldg(b2 + col + 1);
#pragma unroll
            for (int mt = 0; mt < 2; mt++) {
                int r0 = m0 + wm + mt * 16 + g;
                if (r0 < NN) {
                    float2 o0 = make_float2(acc[mt][nt][0] + bx, acc[mt][nt][1] + by);
                    *(float2*)(hout + (size_t)r0 * DD + col) = o0;
                }
                if (r0 + 8 < NN) {
                    float2 o1 = make_float2(acc[mt][nt][2] + bx, acc[mt][nt][3] + by);
                    *(float2*)(hout + (size_t)(r0 + 8) * DD + col) = o1;
                }
            }
        }
    }
}

// ---------------- pooling ----------------
__global__ void pool_kernel(const int* __restrict__ batch) {
    __shared__ float inv[BB];
    int tid = threadIdx.x;  // 384 threads
    if (tid < BB) inv[tid] = 1.f / (float)max(g_counts[tid], 1);
    __syncthreads();
    int layer = tid >> 7;
    int col   = tid & 127;
    const float* h = g_h[layer];
    float acc = 0.f;
    for (int row = blockIdx.x; row < NN; row += gridDim.x)
        acc += h[(size_t)row * DD + col] * inv[batch[row]];
    atomicAdd(&g_G[tid], acc);
}

// ---------------- final tiny MLP ----------------
__global__ void final_kernel(const float* __restrict__ l1w, const float* __restrict__ l1b,
                             const float* __restrict__ l2w, const float* __restrict__ l2b,
                             float* __restrict__ out) {
    __shared__ float Gs[LL * DD];
    __shared__ float g1[DD];
    int tid = threadIdx.x;  // 128
    for (int i = tid; i < LL * DD; i += 128) Gs[i] = g_G[i];
    __syncthreads();
    float acc = l1b[tid];
    for (int k = 0; k < LL * DD; k++) acc += Gs[k] * l1w[k * DD + tid];
    g1[tid] = fmaxf(acc, 0.f);
    __syncthreads();
    if (tid < OUTD) {
        float a2 = l2b[tid];
        for (int k = 0; k < DD; k++) a2 += g1[k] * l2w[k * OUTD + tid];
        out[tid] = fmaxf(a2, 0.f);
    }
}

// ---------------- launch ----------------
extern "C" void kernel_launch(void* const* d_in, const int* in_sizes, int n_in,
                              void* d_out, int out_size) {
    const float* x    = (const float*)d_in[0];
    const int*   ei   = (const int*)d_in[1];
    const int*   batch= (const int*)d_in[2];
    const float* eps  = (const float*)d_in[3];
    const float* W1   = (const float*)d_in[4];
    const float* b1   = (const float*)d_in[5];
    const float* W2   = (const float*)d_in[6];
    const float* b2   = (const float*)d_in[7];
    const float* l1w  = (const float*)d_in[8];
    const float* l1b  = (const float*)d_in[9];
    const float* l2w  = (const float*)d_in[10];
    const float* l2b  = (const float*)d_in[11];
    float* out = (float*)d_out;

    cudaFuncSetAttribute(mlp_kernel, cudaFuncAttributeMaxDynamicSharedMemorySize, MLP_SMEM);

    zero_kernel<<<(NN + 255) / 256, 256>>>();
    hist_kernel<<<(EE + 255) / 256, 256>>>(ei + EE);
    batch_hist_kernel<<<64, 256>>>(batch);
    scan1_kernel<<<SCAN_B, 256>>>();
    scan2_kernel<<<1, 256>>>();
    scan3_kernel<<<SCAN_B, 256>>>();
    scatter_kernel<<<(EE + 255) / 256, 256>>>(ei, ei + EE);

    for (int l = 0; l < LL; l++) {
        agg_kernel<<<(NN * 32 + 255) / 256, 256>>>(x, eps, l);
        mlp_kernel<<<(NN + 127) / 128, 256, MLP_SMEM>>>(l, W1, b1, W2, b2);
    }

    pool_kernel<<<256, 384>>>(batch);
    final_kernel<<<1, 128>>>(l1w, l1b, l2w, l2b, out);
}

// round 3
// speedup vs baseline: 1.6237x; 1.0203x over previous
#include <cuda_runtime.h>
#include <cuda_fp16.h>
#include <cstdint>

#define NN   50000
#define EE   1600000
#define BB   64
#define DD   128
#define LL   3
#define OUTD 64

#define SCAN_B 196          // ceil(50000/256)

// ---------------- scratch (static device allocations) ----------------
__device__ int    g_deg[NN];
__device__ int    g_offs[NN + 1];
__device__ int    g_cursor[NN];
__device__ int    g_csr[EE];
__device__ int    g_counts[BB];
__device__ int    g_bsum[SCAN_B];
__device__ int    g_bbase[SCAN_B];
__device__ float  g_G[LL * DD];
__device__ float  g_z[NN * DD];
__device__ float  g_h[LL][NN * DD];
__device__ __half g_x16[NN * DD];
__device__ __half g_h16[LL][NN * DD];

// ---------------- setup kernels ----------------
__global__ void zero_kernel() {
    int i = blockIdx.x * blockDim.x + threadIdx.x;
    if (i < NN) g_deg[i] = 0;
    if (i < BB) g_counts[i] = 0;
    if (i < LL * DD) g_G[i] = 0.f;
}

__global__ void conv_x_kernel(const float* __restrict__ x) {
    int i = blockIdx.x * blockDim.x + threadIdx.x;   // one float4 per thread
    if (i >= NN * DD / 4) return;
    float4 v = ((const float4*)x)[i];
    __half2* o = (__half2*)(g_x16 + (size_t)i * 4);
    o[0] = __floats2half2_rn(v.x, v.y);
    o[1] = __floats2half2_rn(v.z, v.w);
}

__global__ void hist_kernel(const int* __restrict__ dst) {
    int i = blockIdx.x * blockDim.x + threadIdx.x;
    if (i < EE) atomicAdd(&g_deg[dst[i]], 1);
}

__global__ void batch_hist_kernel(const int* __restrict__ batch) {
    __shared__ int loc[BB];
    if (threadIdx.x < BB) loc[threadIdx.x] = 0;
    __syncthreads();
    for (int i = blockIdx.x * blockDim.x + threadIdx.x; i < NN; i += gridDim.x * blockDim.x)
        atomicAdd(&loc[batch[i]], 1);
    __syncthreads();
    if (threadIdx.x < BB) atomicAdd(&g_counts[threadIdx.x], loc[threadIdx.x]);
}

// ---- parallel scan: S1 block sums, S2 scan of sums, S3 per-block rescan ----
__global__ void scan1_kernel() {
    int i = blockIdx.x * 256 + threadIdx.x;
    int v = (i < NN) ? g_deg[i] : 0;
#pragma unroll
    for (int d = 16; d > 0; d >>= 1) v += __shfl_down_sync(0xffffffffu, v, d);
    __shared__ int ws[8];
    if ((threadIdx.x & 31) == 0) ws[threadIdx.x >> 5] = v;
    __syncthreads();
    if (threadIdx.x < 8) {
        int t = ws[threadIdx.x];
#pragma unroll
        for (int d = 4; d > 0; d >>= 1) t += __shfl_down_sync(0xffu, t, d);
        if (threadIdx.x == 0) g_bsum[blockIdx.x] = t;
    }
}

__global__ void scan2_kernel() {
    __shared__ int sh[256];
    int tid = threadIdx.x;
    int v = (tid < SCAN_B) ? g_bsum[tid] : 0;
    sh[tid] = v;
    __syncthreads();
    for (int d = 1; d < 256; d <<= 1) {
        int t = (tid >= d) ? sh[tid - d] : 0;
        __syncthreads();
        sh[tid] += t;
        __syncthreads();
    }
    if (tid < SCAN_B) g_bbase[tid] = sh[tid] - v;
    if (tid == 0) g_offs[NN] = EE;
}

__global__ void scan3_kernel() {
    __shared__ int sh[256];
    int tid = threadIdx.x;
    int i = blockIdx.x * 256 + tid;
    int v = (i < NN) ? g_deg[i] : 0;
    sh[tid] = v;
    __syncthreads();
    for (int d = 1; d < 256; d <<= 1) {
        int t = (tid >= d) ? sh[tid - d] : 0;
        __syncthreads();
        sh[tid] += t;
        __syncthreads();
    }
    if (i < NN) {
        int o = g_bbase[blockIdx.x] + sh[tid] - v;
        g_offs[i] = o;
        g_cursor[i] = o;
    }
}

__global__ void scatter_kernel(const int* __restrict__ src, const int* __restrict__ dst) {
    int i = blockIdx.x * blockDim.x + threadIdx.x;
    if (i < EE) {
        int p = atomicAdd(&g_cursor[dst[i]], 1);
        g_csr[p] = src[i];
    }
}

// ---------------- aggregation: warp per node, fp16 gather, fp32 accumulate ----------------
__global__ void agg_kernel(const float* __restrict__ x, const float* __restrict__ eps, int l) {
    int gw = (blockIdx.x * blockDim.x + threadIdx.x) >> 5;
    if (gw >= NN) return;
    int lane = threadIdx.x & 31;

    const float*  hin32 = (l == 0) ? x : g_h[l - 1];
    const __half* hin16 = (l == 0) ? g_x16 : g_h16[l - 1];
    const uint2* hp = (const uint2*)hin16;   // 4 halves per uint2, row = 32 uint2

    float ep1 = 1.0f + eps[l];
    float4 self = ((const float4*)hin32)[(size_t)gw * 32 + lane];
    float4 acc;
    acc.x = self.x * ep1; acc.y = self.y * ep1; acc.z = self.z * ep1; acc.w = self.w * ep1;

    int s = g_offs[gw], e = g_offs[gw + 1];
    int j = s;
    for (; j + 8 <= e; j += 8) {
        int idx0 = g_csr[j],     idx1 = g_csr[j + 1], idx2 = g_csr[j + 2], idx3 = g_csr[j + 3];
        int idx4 = g_csr[j + 4], idx5 = g_csr[j + 5], idx6 = g_csr[j + 6], idx7 = g_csr[j + 7];
        uint2 v0 = hp[(size_t)idx0 * 32 + lane];
        uint2 v1 = hp[(size_t)idx1 * 32 + lane];
        uint2 v2 = hp[(size_t)idx2 * 32 + lane];
        uint2 v3 = hp[(size_t)idx3 * 32 + lane];
        uint2 v4 = hp[(size_t)idx4 * 32 + lane];
        uint2 v5 = hp[(size_t)idx5 * 32 + lane];
        uint2 v6 = hp[(size_t)idx6 * 32 + lane];
        uint2 v7 = hp[(size_t)idx7 * 32 + lane];
#pragma unroll
        for (int q = 0; q < 8; q++) {
            uint2 v = (q == 0) ? v0 : (q == 1) ? v1 : (q == 2) ? v2 : (q == 3) ? v3
                    : (q == 4) ? v4 : (q == 5) ? v5 : (q == 6) ? v6 : v7;
            float2 fa = __half22float2(*reinterpret_cast<__half2*>(&v.x));
            float2 fb = __half22float2(*reinterpret_cast<__half2*>(&v.y));
            acc.x += fa.x; acc.y += fa.y; acc.z += fb.x; acc.w += fb.y;
        }
    }
    for (; j < e; j++) {
        uint2 v = hp[(size_t)g_csr[j] * 32 + lane];
        float2 fa = __half22float2(*reinterpret_cast<__half2*>(&v.x));
        float2 fb = __half22float2(*reinterpret_cast<__half2*>(&v.y));
        acc.x += fa.x; acc.y += fa.y; acc.z += fb.x; acc.w += fb.y;
    }
    ((float4*)g_z)[(size_t)gw * 32 + lane] = acc;
}

// ---------------- TF32 tensor-core fused MLP ----------------
#define ZLD 132   // Zs row stride (floats): 132 % 32 == 4 -> A-frag conflict-free
#define WLD 136   // Ws row stride (floats): 136 % 32 == 8 -> B-frag conflict-free
#define MLP_SMEM ((128 * ZLD + 128 * WLD) * 4)

__device__ __forceinline__ uint32_t tf32r(float x) {
    uint32_t r;
    asm("cvt.rna.tf32.f32 %0, %1;" : "=r"(r) : "f"(x));
    return r;
}

__device__ __forceinline__ void mma_tf32(float c[4], const uint32_t a[4], const uint32_t b[2]) {
    asm volatile(
        "mma.sync.aligned.m16n8k8.row.col.f32.tf32.tf32.f32 "
        "{%0,%1,%2,%3}, {%4,%5,%6,%7}, {%8,%9}, {%0,%1,%2,%3};\n"
        : "+f"(c[0]), "+f"(c[1]), "+f"(c[2]), "+f"(c[3])
        : "r"(a[0]), "r"(a[1]), "r"(a[2]), "r"(a[3]), "r"(b[0]), "r"(b[1]));
}

__device__ __forceinline__ void gemm_tile(const float* __restrict__ Zs, const float* __restrict__ Ws,
                                          float acc[2][8][4], int wm, int wn, int lane) {
    int g = lane >> 2, t = lane & 3;
#pragma unroll
    for (int k0 = 0; k0 < 128; k0 += 8) {
        uint32_t a[2][4];
#pragma unroll
        for (int mt = 0; mt < 2; mt++) {
            int r0 = wm + mt * 16 + g;
            a[mt][0] = __float_as_uint(Zs[r0 * ZLD + k0 + t]);
            a[mt][1] = __float_as_uint(Zs[(r0 + 8) * ZLD + k0 + t]);
            a[mt][2] = __float_as_uint(Zs[r0 * ZLD + k0 + t + 4]);
            a[mt][3] = __float_as_uint(Zs[(r0 + 8) * ZLD + k0 + t + 4]);
        }
        uint32_t b[8][2];
#pragma unroll
        for (int nt = 0; nt < 8; nt++) {
            int c = wn + nt * 8 + g;
            b[nt][0] = __float_as_uint(Ws[(k0 + t) * WLD + c]);
            b[nt][1] = __float_as_uint(Ws[(k0 + 4 + t) * WLD + c]);
        }
#pragma unroll
        for (int mt = 0; mt < 2; mt++)
#pragma unroll
            for (int nt = 0; nt < 8; nt++)
                mma_tf32(acc[mt][nt], a[mt], b[nt]);
    }
}

__global__ __launch_bounds__(256, 1) void mlp_kernel(
    int l,
    const float* __restrict__ W1g, const float* __restrict__ b1g,
    const float* __restrict__ W2g, const float* __restrict__ b2g) {
    extern __shared__ float smem[];
    float* Zs = smem;               // [128][ZLD]
    float* Ws = smem + 128 * ZLD;   // [128][WLD]
    const float* W1 = W1g + (size_t)l * DD * DD;
    const float* W2 = W2g + (size_t)l * DD * DD;
    const float* b1 = b1g + l * DD;
    const float* b2 = b2g + l * DD;
    float*  hout  = g_h[l];
    __half* hout16 = g_h16[l];

    int tid  = threadIdx.x;
    int lane = tid & 31;
    int w    = tid >> 5;
    int wm   = (w & 3) * 32;
    int wn   = (w >> 2) * 64;
    int m0   = blockIdx.x * 128;

    // cooperative load: Z tile (tf32-rounded) and W1
#pragma unroll
    for (int i = 0; i < 16; i++) {
        int idx = i * 256 + tid;        // 0..4095
        int row = idx >> 5;
        int c4  = (idx & 31) * 4;
        float4 v = make_float4(0.f, 0.f, 0.f, 0.f);
        if (m0 + row < NN) v = *(const float4*)(g_z + (size_t)(m0 + row) * DD + c4);
        float* dz = Zs + row * ZLD + c4;
        dz[0] = __uint_as_float(tf32r(v.x));
        dz[1] = __uint_as_float(tf32r(v.y));
        dz[2] = __uint_as_float(tf32r(v.z));
        dz[3] = __uint_as_float(tf32r(v.w));
        float4 wv = *(const float4*)(W1 + row * DD + c4);
        float* dw = Ws + row * WLD + c4;
        dw[0] = __uint_as_float(tf32r(wv.x));
        dw[1] = __uint_as_float(tf32r(wv.y));
        dw[2] = __uint_as_float(tf32r(wv.z));
        dw[3] = __uint_as_float(tf32r(wv.w));
    }
    __syncthreads();

    float acc[2][8][4];
#pragma unroll
    for (int mt = 0; mt < 2; mt++)
#pragma unroll
        for (int nt = 0; nt < 8; nt++)
#pragma unroll
            for (int i = 0; i < 4; i++) acc[mt][nt][i] = 0.f;

    gemm_tile(Zs, Ws, acc, wm, wn, lane);
    __syncthreads();

    // epilogue1: relu(acc + b1) -> Zs (tf32-rounded); reload Ws with W2
    {
        int g = lane >> 2, t = lane & 3;
#pragma unroll
        for (int nt = 0; nt < 8; nt++) {
            int col = wn + nt * 8 + 2 * t;
            float bx = __ldg(b1 + col), by = __ldg(b1 + col + 1);
#pragma unroll
            for (int mt = 0; mt < 2; mt++) {
                int r0 = wm + mt * 16 + g;
                Zs[r0 * ZLD + col]           = __uint_as_float(tf32r(fmaxf(acc[mt][nt][0] + bx, 0.f)));
                Zs[r0 * ZLD + col + 1]       = __uint_as_float(tf32r(fmaxf(acc[mt][nt][1] + by, 0.f)));
                Zs[(r0 + 8) * ZLD + col]     = __uint_as_float(tf32r(fmaxf(acc[mt][nt][2] + bx, 0.f)));
                Zs[(r0 + 8) * ZLD + col + 1] = __uint_as_float(tf32r(fmaxf(acc[mt][nt][3] + by, 0.f)));
            }
        }
    }
#pragma unroll
    for (int i = 0; i < 16; i++) {
        int idx = i * 256 + tid;
        int row = idx >> 5;
        int c4  = (idx & 31) * 4;
        float4 wv = *(const float4*)(W2 + row * DD + c4);
        float* dw = Ws + row * WLD + c4;
        dw[0] = __uint_as_float(tf32r(wv.x));
        dw[1] = __uint_as_float(tf32r(wv.y));
        dw[2] = __uint_as_float(tf32r(wv.z));
        dw[3] = __uint_as_float(tf32r(wv.w));
    }
    __syncthreads();

#pragma unroll
    for (int mt = 0; mt < 2; mt++)
#pragma unroll
        for (int nt = 0; nt < 8; nt++)
#pragma unroll
            for (int i = 0; i < 4; i++) acc[mt][nt][i] = 0.f;

    gemm_tile(Zs, Ws, acc, wm, wn, lane);

    // epilogue2: acc + b2 -> global h (fp32) and h16 (fp16)
    {
        int g = lane >> 2, t = lane & 3;
#pragma unroll
        for (int nt = 0; nt < 8; nt++) {
            int col = wn + nt * 8 + 2 * t;
            float bx = __ldg(b2 + col), by = __ldg(b2 + col + 1);
#pragma unroll
            for (int mt = 0; mt < 2; mt++) {
                int r0 = m0 + wm + mt * 16 + g;
                if (r0 < NN) {
                    float ox = acc[mt][nt][0] + bx, oy = acc[mt][nt][1] + by;
                    *(float2*)(hout + (size_t)r0 * DD + col) = make_float2(ox, oy);
                    *(__half2*)(hout16 + (size_t)r0 * DD + col) = __floats2half2_rn(ox, oy);
                }
                if (r0 + 8 < NN) {
                    float ox = acc[mt][nt][2] + bx, oy = acc[mt][nt][3] + by;
                    *(float2*)(hout + (size_t)(r0 + 8) * DD + col) = make_float2(ox, oy);
                    *(__half2*)(hout16 + (size_t)(r0 + 8) * DD + col) = __floats2half2_rn(ox, oy);
                }
            }
        }
    }
}

// ---------------- pooling ----------------
__global__ void pool_kernel(const int* __restrict__ batch) {
    __shared__ float inv[BB];
    int tid = threadIdx.x;  // 384 threads
    if (tid < BB) inv[tid] = 1.f / (float)max(g_counts[tid], 1);
    __syncthreads();
    int layer = tid >> 7;
    int col   = tid & 127;
    const float* h = g_h[layer];
    float acc = 0.f;
    for (int row = blockIdx.x; row < NN; row += gridDim.x)
        acc += h[(size_t)row * DD + col] * inv[batch[row]];
    atomicAdd(&g_G[tid], acc);
}

// ---------------- final tiny MLP ----------------
__global__ void final_kernel(const float* __restrict__ l1w, const float* __restrict__ l1b,
                             const float* __restrict__ l2w, const float* __restrict__ l2b,
                             float* __restrict__ out) {
    __shared__ float Gs[LL * DD];
    __shared__ float g1[DD];
    int tid = threadIdx.x;  // 128
    for (int i = tid; i < LL * DD; i += 128) Gs[i] = g_G[i];
    __syncthreads();
    float acc = l1b[tid];
    for (int k = 0; k < LL * DD; k++) acc += Gs[k] * l1w[k * DD + tid];
    g1[tid] = fmaxf(acc, 0.f);
    __syncthreads();
    if (tid < OUTD) {
        float a2 = l2b[tid];
        for (int k = 0; k < DD; k++) a2 += g1[k] * l2w[k * OUTD + tid];
        out[tid] = fmaxf(a2, 0.f);
    }
}

// ---------------- launch ----------------
extern "C" void kernel_launch(void* const* d_in, const int* in_sizes, int n_in,
                              void* d_out, int out_size) {
    const float* x    = (const float*)d_in[0];
    const int*   ei   = (const int*)d_in[1];
    const int*   batch= (const int*)d_in[2];
    const float* eps  = (const float*)d_in[3];
    const float* W1   = (const float*)d_in[4];
    const float* b1   = (const float*)d_in[5];
    const float* W2   = (const float*)d_in[6];
    const float* b2   = (const float*)d_in[7];
    const float* l1w  = (const float*)d_in[8];
    const float* l1b  = (const float*)d_in[9];
    const float* l2w  = (const float*)d_in[10];
    const float* l2b  = (const float*)d_in[11];
    float* out = (float*)d_out;

    cudaFuncSetAttribute(mlp_kernel, cudaFuncAttributeMaxDynamicSharedMemorySize, MLP_SMEM);

    zero_kernel<<<(NN + 255) / 256, 256>>>();
    conv_x_kernel<<<(NN * DD / 4 + 255) / 256, 256>>>(x);
    hist_kernel<<<(EE + 255) / 256, 256>>>(ei + EE);
    batch_hist_kernel<<<64, 256>>>(batch);
    scan1_kernel<<<SCAN_B, 256>>>();
    scan2_kernel<<<1, 256>>>();
    scan3_kernel<<<SCAN_B, 256>>>();
    scatter_kernel<<<(EE + 255) / 256, 256>>>(ei, ei + EE);

    for (int l = 0; l < LL; l++) {
        agg_kernel<<<(NN * 32 + 255) / 256, 256>>>(x, eps, l);
        mlp_kernel<<<(NN + 127) / 128, 256, MLP_SMEM>>>(l, W1, b1, W2, b2);
    }

    pool_kernel<<<256, 384>>>(batch);
    final_kernel<<<1, 128>>>(l1w, l1b, l2w, l2b, out);
}

// round 4
// speedup vs baseline: 1.9322x; 1.1900x over previous
#include <cuda_runtime.h>
#include <cuda_fp16.h>
#include <cstdint>

#define NN   50000
#define EE   1600000
#define BB   64
#define DD   128
#define LL   3
#define OUTD 64

#define SCAN_B 196          // ceil(50000/256)

// ---------------- scratch (static device allocations) ----------------
__device__ int    g_deg[NN];
__device__ int    g_offs[NN + 1];
__device__ int    g_cursor[NN];
__device__ int    g_csr[EE];
__device__ int    g_counts[BB];
__device__ int    g_bsum[SCAN_B];
__device__ int    g_bbase[SCAN_B];
__device__ float  g_G[LL * DD];
__device__ float  g_z[NN * DD];
__device__ __half g_x16[NN * DD];
__device__ __half g_h16[LL][NN * DD];
__device__ __half g_w1t[LL * DD * DD];   // transposed [n][k] fp16
__device__ __half g_w2t[LL * DD * DD];   // transposed [n][k] fp16

// ---------------- setup kernels ----------------
__global__ void zero_kernel() {
    int i = blockIdx.x * blockDim.x + threadIdx.x;
    if (i < NN) g_deg[i] = 0;
    if (i < BB) g_counts[i] = 0;
    if (i < LL * DD) g_G[i] = 0.f;
}

__global__ void conv_x_kernel(const float* __restrict__ x) {
    int i = blockIdx.x * blockDim.x + threadIdx.x;   // one float4 per thread
    if (i >= NN * DD / 4) return;
    float4 v = ((const float4*)x)[i];
    __half2* o = (__half2*)(g_x16 + (size_t)i * 4);
    o[0] = __floats2half2_rn(v.x, v.y);
    o[1] = __floats2half2_rn(v.z, v.w);
}

// transpose + fp16-convert weights: g_wXt[l][n*DD + k] = (half)WX[l][k*DD + n]
__global__ void w16_kernel(const float* __restrict__ W1g, const float* __restrict__ W2g) {
    int i = blockIdx.x * blockDim.x + threadIdx.x;   // one half2 (k,k+1) per thread
    if (i >= LL * DD * DD / 2) return;
    int l  = i / (DD * DD / 2);
    int r  = i % (DD * DD / 2);
    int n  = r / (DD / 2);
    int k  = (r % (DD / 2)) * 2;
    size_t gb = (size_t)l * DD * DD;
    float a0 = W1g[gb + (size_t)k * DD + n];
    float a1 = W1g[gb + (size_t)(k + 1) * DD + n];
    *(__half2*)(g_w1t + gb + (size_t)n * DD + k) = __floats2half2_rn(a0, a1);
    float b0v = W2g[gb + (size_t)k * DD + n];
    float b1v = W2g[gb + (size_t)(k + 1) * DD + n];
    *(__half2*)(g_w2t + gb + (size_t)n * DD + k) = __floats2half2_rn(b0v, b1v);
}

__global__ void hist_kernel(const int* __restrict__ dst) {
    int i = blockIdx.x * blockDim.x + threadIdx.x;
    if (i < EE) atomicAdd(&g_deg[dst[i]], 1);
}

__global__ void batch_hist_kernel(const int* __restrict__ batch) {
    __shared__ int loc[BB];
    if (threadIdx.x < BB) loc[threadIdx.x] = 0;
    __syncthreads();
    for (int i = blockIdx.x * blockDim.x + threadIdx.x; i < NN; i += gridDim.x * blockDim.x)
        atomicAdd(&loc[batch[i]], 1);
    __syncthreads();
    if (threadIdx.x < BB) atomicAdd(&g_counts[threadIdx.x], loc[threadIdx.x]);
}

// ---- parallel scan: S1 block sums, S2 scan of sums, S3 per-block rescan ----
__global__ void scan1_kernel() {
    int i = blockIdx.x * 256 + threadIdx.x;
    int v = (i < NN) ? g_deg[i] : 0;
#pragma unroll
    for (int d = 16; d > 0; d >>= 1) v += __shfl_down_sync(0xffffffffu, v, d);
    __shared__ int ws[8];
    if ((threadIdx.x & 31) == 0) ws[threadIdx.x >> 5] = v;
    __syncthreads();
    if (threadIdx.x < 8) {
        int t = ws[threadIdx.x];
#pragma unroll
        for (int d = 4; d > 0; d >>= 1) t += __shfl_down_sync(0xffu, t, d);
        if (threadIdx.x == 0) g_bsum[blockIdx.x] = t;
    }
}

__global__ void scan2_kernel() {
    __shared__ int sh[256];
    int tid = threadIdx.x;
    int v = (tid < SCAN_B) ? g_bsum[tid] : 0;
    sh[tid] = v;
    __syncthreads();
    for (int d = 1; d < 256; d <<= 1) {
        int t = (tid >= d) ? sh[tid - d] : 0;
        __syncthreads();
        sh[tid] += t;
        __syncthreads();
    }
    if (tid < SCAN_B) g_bbase[tid] = sh[tid] - v;
    if (tid == 0) g_offs[NN] = EE;
}

__global__ void scan3_kernel() {
    __shared__ int sh[256];
    int tid = threadIdx.x;
    int i = blockIdx.x * 256 + tid;
    int v = (i < NN) ? g_deg[i] : 0;
    sh[tid] = v;
    __syncthreads();
    for (int d = 1; d < 256; d <<= 1) {
        int t = (tid >= d) ? sh[tid - d] : 0;
        __syncthreads();
        sh[tid] += t;
        __syncthreads();
    }
    if (i < NN) {
        int o = g_bbase[blockIdx.x] + sh[tid] - v;
        g_offs[i] = o;
        g_cursor[i] = o;
    }
}

__global__ void scatter_kernel(const int* __restrict__ src, const int* __restrict__ dst) {
    int i = blockIdx.x * blockDim.x + threadIdx.x;
    if (i < EE) {
        int p = atomicAdd(&g_cursor[dst[i]], 1);
        g_csr[p] = src[i];
    }
}

// ---------------- aggregation: HALF-warp (16 lanes) per node, uint4 fp16 gather ----
__global__ void agg_kernel(const float* __restrict__ eps, int l) {
    int node = (blockIdx.x * blockDim.x + threadIdx.x) >> 4;
    if (node >= NN) return;
    int lane = threadIdx.x & 15;

    const __half* hin16 = (l == 0) ? g_x16 : g_h16[l - 1];
    const uint4* hp = (const uint4*)hin16;   // 8 halves per uint4, row = 16 uint4

    float ep1 = 1.0f + eps[l];
    float acc[8];
    {
        uint4 sv = hp[(size_t)node * 16 + lane];
        const __half2* s = (const __half2*)&sv;
#pragma unroll
        for (int q = 0; q < 4; q++) {
            float2 f = __half22float2(s[q]);
            acc[2 * q]     = f.x * ep1;
            acc[2 * q + 1] = f.y * ep1;
        }
    }

    int s = g_offs[node], e = g_offs[node + 1];
    int j = s;
    for (; j + 4 <= e; j += 4) {
        int i0 = g_csr[j], i1 = g_csr[j + 1], i2 = g_csr[j + 2], i3 = g_csr[j + 3];
        uint4 v0 = hp[(size_t)i0 * 16 + lane];
        uint4 v1 = hp[(size_t)i1 * 16 + lane];
        uint4 v2 = hp[(size_t)i2 * 16 + lane];
        uint4 v3 = hp[(size_t)i3 * 16 + lane];
#pragma unroll
        for (int q = 0; q < 4; q++) {
            uint32_t u0 = (&v0.x)[q], u1 = (&v1.x)[q], u2 = (&v2.x)[q], u3 = (&v3.x)[q];
            float2 f0 = __half22float2(*reinterpret_cast<__half2*>(&u0));
            float2 f1 = __half22float2(*reinterpret_cast<__half2*>(&u1));
            float2 f2 = __half22float2(*reinterpret_cast<__half2*>(&u2));
            float2 f3 = __half22float2(*reinterpret_cast<__half2*>(&u3));
            acc[2 * q]     += (f0.x + f1.x) + (f2.x + f3.x);
            acc[2 * q + 1] += (f0.y + f1.y) + (f2.y + f3.y);
        }
    }
    for (; j < e; j++) {
        uint4 v = hp[(size_t)g_csr[j] * 16 + lane];
#pragma unroll
        for (int q = 0; q < 4; q++) {
            uint32_t u = (&v.x)[q];
            float2 f = __half22float2(*reinterpret_cast<__half2*>(&u));
            acc[2 * q]     += f.x;
            acc[2 * q + 1] += f.y;
        }
    }

    float4* zp = (float4*)g_z;
    zp[(size_t)node * 32 + lane * 2]     = make_float4(acc[0], acc[1], acc[2], acc[3]);
    zp[(size_t)node * 32 + lane * 2 + 1] = make_float4(acc[4], acc[5], acc[6], acc[7]);
}

// ---------------- fp16 tensor-core fused MLP ----------------
#define ZP 136                 // halves per smem row (stride 272B = 68 words)
#define MLP_SMEM (2 * 128 * ZP * 2)

__device__ __forceinline__ void mma_f16(float c[4], const uint32_t a[4], const uint32_t b[2]) {
    asm volatile(
        "mma.sync.aligned.m16n8k16.row.col.f32.f16.f16.f32 "
        "{%0,%1,%2,%3}, {%4,%5,%6,%7}, {%8,%9}, {%0,%1,%2,%3};\n"
        : "+f"(c[0]), "+f"(c[1]), "+f"(c[2]), "+f"(c[3])
        : "r"(a[0]), "r"(a[1]), "r"(a[2]), "r"(a[3]), "r"(b[0]), "r"(b[1]));
}

// acc += Zs[m][k] @ Ws[n][k]^T   (both fp16 smem tiles, ZP-stride rows)
__device__ __forceinline__ void gemm_tile16(const __half* __restrict__ Zs, const __half* __restrict__ Ws,
                                            float acc[2][8][4], int wm, int wn, int lane) {
    int g = lane >> 2, t = lane & 3;
#pragma unroll
    for (int k0 = 0; k0 < 128; k0 += 16) {
        uint32_t a[2][4];
#pragma unroll
        for (int mt = 0; mt < 2; mt++) {
            int r0 = wm + mt * 16 + g;
            a[mt][0] = *(const uint32_t*)(Zs + r0 * ZP + k0 + 2 * t);
            a[mt][1] = *(const uint32_t*)(Zs + (r0 + 8) * ZP + k0 + 2 * t);
            a[mt][2] = *(const uint32_t*)(Zs + r0 * ZP + k0 + 8 + 2 * t);
            a[mt][3] = *(const uint32_t*)(Zs + (r0 + 8) * ZP + k0 + 8 + 2 * t);
        }
        uint32_t b[8][2];
#pragma unroll
        for (int nt = 0; nt < 8; nt++) {
            int c = wn + nt * 8 + g;
            b[nt][0] = *(const uint32_t*)(Ws + c * ZP + k0 + 2 * t);
            b[nt][1] = *(const uint32_t*)(Ws + c * ZP + k0 + 8 + 2 * t);
        }
#pragma unroll
        for (int mt = 0; mt < 2; mt++)
#pragma unroll
            for (int nt = 0; nt < 8; nt++)
                mma_f16(acc[mt][nt], a[mt], b[nt]);
    }
}

__global__ __launch_bounds__(256, 2) void mlp_kernel(
    int l,
    const float* __restrict__ b1g, const float* __restrict__ b2g) {
    extern __shared__ __half hsm[];
    __half* Zs = hsm;             // [128][ZP]
    __half* Ws = hsm + 128 * ZP;  // [128][ZP]  (W^T: [n][k])
    const __half* W1t = g_w1t + (size_t)l * DD * DD;
    const __half* W2t = g_w2t + (size_t)l * DD * DD;
    const float* b1 = b1g + l * DD;
    const float* b2 = b2g + l * DD;
    __half* hout16 = g_h16[l];

    int tid  = threadIdx.x;
    int lane = tid & 31;
    int w    = tid >> 5;
    int wm   = (w & 3) * 32;
    int wn   = (w >> 2) * 64;
    int m0   = blockIdx.x * 128;

    // load Z tile (fp32 -> fp16) : 4096 float4s
#pragma unroll
    for (int i = 0; i < 16; i++) {
        int idx = i * 256 + tid;
        int row = idx >> 5;
        int c4  = (idx & 31) * 4;
        float4 v = make_float4(0.f, 0.f, 0.f, 0.f);
        if (m0 + row < NN) v = *(const float4*)(g_z + (size_t)(m0 + row) * DD + c4);
        __half2* dz = (__half2*)(Zs + row * ZP + c4);
        dz[0] = __floats2half2_rn(v.x, v.y);
        dz[1] = __floats2half2_rn(v.z, v.w);
    }
    // load W1^T : 2048 uint4s (8 halves each)
#pragma unroll
    for (int i = 0; i < 8; i++) {
        int idx = i * 256 + tid;
        int row = idx >> 4;
        int c8  = (idx & 15) * 8;
        *(uint4*)(Ws + row * ZP + c8) = *(const uint4*)(W1t + (size_t)row * DD + c8);
    }
    __syncthreads();

    float acc[2][8][4];
#pragma unroll
    for (int mt = 0; mt < 2; mt++)
#pragma unroll
        for (int nt = 0; nt < 8; nt++)
#pragma unroll
            for (int i = 0; i < 4; i++) acc[mt][nt][i] = 0.f;

    gemm_tile16(Zs, Ws, acc, wm, wn, lane);
    __syncthreads();

    // epilogue1: relu(acc + b1) -> Zs (fp16); reload Ws with W2^T
    {
        int g = lane >> 2, t = lane & 3;
#pragma unroll
        for (int nt = 0; nt < 8; nt++) {
            int col = wn + nt * 8 + 2 * t;
            float bx = __ldg(b1 + col), by = __ldg(b1 + col + 1);
#pragma unroll
            for (int mt = 0; mt < 2; mt++) {
                int r0 = wm + mt * 16 + g;
                *(__half2*)(Zs + r0 * ZP + col) =
                    __floats2half2_rn(fmaxf(acc[mt][nt][0] + bx, 0.f), fmaxf(acc[mt][nt][1] + by, 0.f));
                *(__half2*)(Zs + (r0 + 8) * ZP + col) =
                    __floats2half2_rn(fmaxf(acc[mt][nt][2] + bx, 0.f), fmaxf(acc[mt][nt][3] + by, 0.f));
            }
        }
    }
#pragma unroll
    for (int i = 0; i < 8; i++) {
        int idx = i * 256 + tid;
        int row = idx >> 4;
        int c8  = (idx & 15) * 8;
        *(uint4*)(Ws + row * ZP + c8) = *(const uint4*)(W2t + (size_t)row * DD + c8);
    }
    __syncthreads();

#pragma unroll
    for (int mt = 0; mt < 2; mt++)
#pragma unroll
        for (int nt = 0; nt < 8; nt++)
#pragma unroll
            for (int i = 0; i < 4; i++) acc[mt][nt][i] = 0.f;

    gemm_tile16(Zs, Ws, acc, wm, wn, lane);

    // epilogue2: acc + b2 -> g_h16 (fp16 only)
    {
        int g = lane >> 2, t = lane & 3;
#pragma unroll
        for (int nt = 0; nt < 8; nt++) {
            int col = wn + nt * 8 + 2 * t;
            float bx = __ldg(b2 + col), by = __ldg(b2 + col + 1);
#pragma unroll
            for (int mt = 0; mt < 2; mt++) {
                int r0 = m0 + wm + mt * 16 + g;
                if (r0 < NN)
                    *(__half2*)(hout16 + (size_t)r0 * DD + col) =
                        __floats2half2_rn(acc[mt][nt][0] + bx, acc[mt][nt][1] + by);
                if (r0 + 8 < NN)
                    *(__half2*)(hout16 + (size_t)(r0 + 8) * DD + col) =
                        __floats2half2_rn(acc[mt][nt][2] + bx, acc[mt][nt][3] + by);
            }
        }
    }
}

// ---------------- pooling (reads fp16 h) ----------------
__global__ void pool_kernel(const int* __restrict__ batch) {
    __shared__ float inv[BB];
    int tid = threadIdx.x;  // 384 threads
    if (tid < BB) inv[tid] = 1.f / (float)max(g_counts[tid], 1);
    __syncthreads();
    int layer = tid >> 7;
    int col   = tid & 127;
    const __half* h = g_h16[layer];
    float acc = 0.f;
    for (int row = blockIdx.x; row < NN; row += gridDim.x)
        acc += __half2float(h[(size_t)row * DD + col]) * inv[batch[row]];
    atomicAdd(&g_G[tid], acc);
}

// ---------------- final tiny MLP ----------------
__global__ void final_kernel(const float* __restrict__ l1w, const float* __restrict__ l1b,
                             const float* __restrict__ l2w, const float* __restrict__ l2b,
                             float* __restrict__ out) {
    __shared__ float Gs[LL * DD];
    __shared__ float g1[DD];
    int tid = threadIdx.x;  // 128
    for (int i = tid; i < LL * DD; i += 128) Gs[i] = g_G[i];
    __syncthreads();
    float acc = l1b[tid];
    for (int k = 0; k < LL * DD; k++) acc += Gs[k] * l1w[k * DD + tid];
    g1[tid] = fmaxf(acc, 0.f);
    __syncthreads();
    if (tid < OUTD) {
        float a2 = l2b[tid];
        for (int k = 0; k < DD; k++) a2 += g1[k] * l2w[k * OUTD + tid];
        out[tid] = fmaxf(a2, 0.f);
    }
}

// ---------------- launch ----------------
extern "C" void kernel_launch(void* const* d_in, const int* in_sizes, int n_in,
                              void* d_out, int out_size) {
    const float* x    = (const float*)d_in[0];
    const int*   ei   = (const int*)d_in[1];
    const int*   batch= (const int*)d_in[2];
    const float* eps  = (const float*)d_in[3];
    const float* W1   = (const float*)d_in[4];
    const float* b1   = (const float*)d_in[5];
    const float* W2   = (const float*)d_in[6];
    const float* b2   = (const float*)d_in[7];
    const float* l1w  = (const float*)d_in[8];
    const float* l1b  = (const float*)d_in[9];
    const float* l2w  = (const float*)d_in[10];
    const float* l2b  = (const float*)d_in[11];
    float* out = (float*)d_out;

    cudaFuncSetAttribute(mlp_kernel, cudaFuncAttributeMaxDynamicSharedMemorySize, MLP_SMEM);

    zero_kernel<<<(NN + 255) / 256, 256>>>();
    conv_x_kernel<<<(NN * DD / 4 + 255) / 256, 256>>>(x);
    w16_kernel<<<(LL * DD * DD / 2 + 255) / 256, 256>>>(W1, W2);
    hist_kernel<<<(EE + 255) / 256, 256>>>(ei + EE);        // <- ncu-profiled slot
    batch_hist_kernel<<<64, 256>>>(batch);
    scan1_kernel<<<SCAN_B, 256>>>();
    scan2_kernel<<<1, 256>>>();
    scan3_kernel<<<SCAN_B, 256>>>();
    scatter_kernel<<<(EE + 255) / 256, 256>>>(ei, ei + EE);

    for (int l = 0; l < LL; l++) {
        agg_kernel<<<(NN * 16 + 255) / 256, 256>>>(eps, l);
        mlp_kernel<<<(NN + 127) / 128, 256, MLP_SMEM>>>(l, b1, b2);
    }

    pool_kernel<<<256, 384>>>(batch);
    final_kernel<<<1, 128>>>(l1w, l1b, l2w, l2b, out);
}